// round 1
// baseline (speedup 1.0000x reference)
#include <cuda_runtime.h>
#include <math.h>

// Problem constants
#define S_LEN   2048
#define NHEADS  16
#define DK      64
#define DMODEL  1024
#define BATCH   2
#define MROWS   (BATCH * S_LEN)   // 4096

// ---------------- scratch (device globals; no allocation) ----------------
__device__ float g_qp[BATCH * NHEADS * S_LEN * DK];   // projected Q  [B,H,S,Dk]
__device__ float g_vp[BATCH * NHEADS * S_LEN * DK];   // projected V  [B,H,S,Dk]
__device__ float g_kp[BATCH * NHEADS * S_LEN * DK];   // projected K  [B,H,S,Dk]
__device__ float g_att[MROWS * DMODEL];               // attention out [B,S,D]

// =====================================================================
// GEMM: C[m,n] = sum_k A[m,k] * W[n,k] + bias[n]     (i.e. x @ W^T + b)
// BM=128 BN=128 BK=16, 256 threads, 8x8 per thread.
// headSplit: store to [B,H,S,Dk] layout instead of row-major [M,N].
// =====================================================================
#define BM 128
#define BN 128
#define BK 16
#define TM 8
#define TN 8

__global__ __launch_bounds__(256) void gemm_bias_kernel(
    const float* __restrict__ A,     // [M,K]
    const float* __restrict__ W,     // [N,K]
    const float* __restrict__ bias,  // [N]
    float* __restrict__ C,
    int M, int N, int K, int headSplit)
{
    __shared__ float As[BK][BM];
    __shared__ float Bs[BK][BN];

    const int tid = threadIdx.x;
    const int tx = tid & 15;
    const int ty = tid >> 4;
    const int blockRow = blockIdx.y * BM;
    const int blockCol = blockIdx.x * BN;

    float acc[TM][TN];
#pragma unroll
    for (int i = 0; i < TM; i++)
#pragma unroll
        for (int j = 0; j < TN; j++) acc[i][j] = 0.f;

    for (int k0 = 0; k0 < K; k0 += BK) {
        // Load A tile (BM x BK) transposed into As[BK][BM]
#pragma unroll
        for (int it = 0; it < 2; it++) {
            int f  = tid + it * 256;        // 0..511 float4 slots
            int m  = f >> 2;                // 0..127
            int kq = (f & 3) * 4;           // 0,4,8,12
            float4 v = *(const float4*)(A + (size_t)(blockRow + m) * K + k0 + kq);
            As[kq + 0][m] = v.x;
            As[kq + 1][m] = v.y;
            As[kq + 2][m] = v.z;
            As[kq + 3][m] = v.w;
        }
        // Load W tile (BN x BK) transposed into Bs[BK][BN]
#pragma unroll
        for (int it = 0; it < 2; it++) {
            int f  = tid + it * 256;
            int n  = f >> 2;
            int kq = (f & 3) * 4;
            float4 v = *(const float4*)(W + (size_t)(blockCol + n) * K + k0 + kq);
            Bs[kq + 0][n] = v.x;
            Bs[kq + 1][n] = v.y;
            Bs[kq + 2][n] = v.z;
            Bs[kq + 3][n] = v.w;
        }
        __syncthreads();

#pragma unroll
        for (int kk = 0; kk < BK; kk++) {
            float a[TM], b[TN];
            *(float4*)&a[0] = *(const float4*)&As[kk][ty * TM];
            *(float4*)&a[4] = *(const float4*)&As[kk][ty * TM + 4];
            *(float4*)&b[0] = *(const float4*)&Bs[kk][tx * TN];
            *(float4*)&b[4] = *(const float4*)&Bs[kk][tx * TN + 4];
#pragma unroll
            for (int i = 0; i < TM; i++)
#pragma unroll
                for (int j = 0; j < TN; j++) acc[i][j] = fmaf(a[i], b[j], acc[i][j]);
        }
        __syncthreads();
    }

    // Epilogue
#pragma unroll
    for (int i = 0; i < TM; i++) {
        int m = blockRow + ty * TM + i;
#pragma unroll
        for (int j = 0; j < TN; j++) {
            int n = blockCol + tx * TN + j;
            float val = acc[i][j] + bias[n];
            if (headSplit) {
                int b = m >> 11;       // m / S_LEN
                int s = m & 2047;      // m % S_LEN
                int h = n >> 6;        // n / DK
                int d = n & 63;        // n % DK
                C[(((size_t)b * NHEADS + h) * S_LEN + s) * DK + d] = val;
            } else {
                C[(size_t)m * N + n] = val;
            }
        }
    }
}

// =====================================================================
// Flash-style attention with the reference's K/V swap:
//   scores = Q @ Vproj^T * scale ; mask==0 -> -1e9 ; softmax ; out = P @ Kproj
// 64-row Q tile, 64-col K tile, Dk=64, online softmax. 256 threads.
// Output stored directly as [B, S, H*Dk] for the final projection.
// =====================================================================
#define AT_Q 64
#define AT_K 64
#define SM_STRIDE 65
#define ATTN_SMEM_BYTES (3 * AT_Q * SM_STRIDE * 4)

__global__ __launch_bounds__(256) void attn_kernel(
    const float* __restrict__ qp,   // [B,H,S,Dk]  projected query
    const float* __restrict__ sp,   // [B,H,S,Dk]  "score keys"  (= projected VALUE)
    const float* __restrict__ op,   // [B,H,S,Dk]  "out values"  (= projected KEY)
    const int*   __restrict__ mask, // [B,S,S]
    float* __restrict__ C)          // [B,S,DMODEL]
{
    extern __shared__ float smem[];
    float* Qs  = smem;                         // [64][65]
    float* KVs = smem + AT_Q * SM_STRIDE;      // [64][65]
    float* Ss  = smem + 2 * AT_Q * SM_STRIDE;  // [64][65]
    __shared__ float m_sm[AT_Q], l_sm[AT_Q], corr_sm[AT_Q];

    const int tid = threadIdx.x;
    const int tx = tid & 15;
    const int ty = tid >> 4;
    const int qt = blockIdx.x;           // 0..31
    const int h  = blockIdx.y;           // 0..15
    const int b  = blockIdx.z;           // 0..1
    const int qbase = qt * AT_Q;
    const float scale = 0.125f;          // 1/sqrt(64)

    const float* qptr  = qp + (((size_t)b * NHEADS + h) * S_LEN + qbase) * DK;
    const float* spb   = sp + (((size_t)b * NHEADS + h) * S_LEN) * DK;
    const float* opb   = op + (((size_t)b * NHEADS + h) * S_LEN) * DK;
    const int*   mbase = mask + (size_t)b * S_LEN * S_LEN;

    // Load Q tile
    for (int i = tid; i < AT_Q * DK / 4; i += 256) {
        int r = i >> 4;
        int c = (i & 15) * 4;
        float4 v = *(const float4*)(qptr + (size_t)r * DK + c);
        float* dst = &Qs[r * SM_STRIDE + c];
        dst[0] = v.x; dst[1] = v.y; dst[2] = v.z; dst[3] = v.w;
    }
    if (tid < AT_Q) { m_sm[tid] = -INFINITY; l_sm[tid] = 0.f; }

    float O[4][4];
#pragma unroll
    for (int i = 0; i < 4; i++)
#pragma unroll
        for (int j = 0; j < 4; j++) O[i][j] = 0.f;

    for (int kt = 0; kt < S_LEN / AT_K; kt++) {
        const int kbase = kt * AT_K;
        __syncthreads();   // previous tile fully consumed (also covers Q load on kt=0)

        // Load V tile (score keys) into KVs
        for (int i = tid; i < AT_K * DK / 4; i += 256) {
            int r = i >> 4;
            int c = (i & 15) * 4;
            float4 v = *(const float4*)(spb + (size_t)(kbase + r) * DK + c);
            float* dst = &KVs[r * SM_STRIDE + c];
            dst[0] = v.x; dst[1] = v.y; dst[2] = v.z; dst[3] = v.w;
        }
        __syncthreads();

        // S = Q @ V^T  (4x4 micro-tile per thread)
        float acc[4][4];
#pragma unroll
        for (int i = 0; i < 4; i++)
#pragma unroll
            for (int j = 0; j < 4; j++) acc[i][j] = 0.f;

#pragma unroll 4
        for (int d = 0; d < DK; d++) {
            float a[4], v[4];
#pragma unroll
            for (int i = 0; i < 4; i++) a[i] = Qs[(ty * 4 + i) * SM_STRIDE + d];
#pragma unroll
            for (int j = 0; j < 4; j++) v[j] = KVs[(tx * 4 + j) * SM_STRIDE + d];
#pragma unroll
            for (int i = 0; i < 4; i++)
#pragma unroll
                for (int j = 0; j < 4; j++) acc[i][j] = fmaf(a[i], v[j], acc[i][j]);
        }

        // scale, mask, write S tile
#pragma unroll
        for (int i = 0; i < 4; i++) {
            int qr = qbase + ty * 4 + i;
            const int* mrow = mbase + (size_t)qr * S_LEN + kbase;
#pragma unroll
            for (int j = 0; j < 4; j++) {
                int kc = tx * 4 + j;
                float s = acc[i][j] * scale;
                if (mrow[kc] == 0) s = -1e9f;
                Ss[(ty * 4 + i) * SM_STRIDE + kc] = s;
            }
        }
        __syncthreads();

        // Load K tile (out values) into KVs — disjoint from softmax's Ss traffic
        for (int i = tid; i < AT_K * DK / 4; i += 256) {
            int r = i >> 4;
            int c = (i & 15) * 4;
            float4 v = *(const float4*)(opb + (size_t)(kbase + r) * DK + c);
            float* dst = &KVs[r * SM_STRIDE + c];
            dst[0] = v.x; dst[1] = v.y; dst[2] = v.z; dst[3] = v.w;
        }

        // Online softmax update: 4 lanes per row
        {
            int r   = tid >> 2;
            int sub = tid & 3;
            float mx = -INFINITY;
#pragma unroll
            for (int cc = 0; cc < 16; cc++)
                mx = fmaxf(mx, Ss[r * SM_STRIDE + sub * 16 + cc]);
            mx = fmaxf(mx, __shfl_xor_sync(0xffffffffu, mx, 1));
            mx = fmaxf(mx, __shfl_xor_sync(0xffffffffu, mx, 2));
            float mo = m_sm[r];
            float mn = fmaxf(mo, mx);
            float ssum = 0.f;
#pragma unroll
            for (int cc = 0; cc < 16; cc++) {
                int idx = r * SM_STRIDE + sub * 16 + cc;
                float e = __expf(Ss[idx] - mn);
                Ss[idx] = e;
                ssum += e;
            }
            ssum += __shfl_xor_sync(0xffffffffu, ssum, 1);
            ssum += __shfl_xor_sync(0xffffffffu, ssum, 2);
            if (sub == 0) {
                float cr = __expf(mo - mn);   // 0 on first tile (mo = -inf)
                corr_sm[r] = cr;
                l_sm[r] = l_sm[r] * cr + ssum;
                m_sm[r] = mn;
            }
        }
        __syncthreads();

        // Rescale + accumulate O += P @ K
#pragma unroll
        for (int i = 0; i < 4; i++) {
            float cr = corr_sm[ty * 4 + i];
#pragma unroll
            for (int j = 0; j < 4; j++) O[i][j] *= cr;
        }
#pragma unroll 4
        for (int kk = 0; kk < AT_K; kk++) {
            float p[4], kv[4];
#pragma unroll
            for (int i = 0; i < 4; i++) p[i] = Ss[(ty * 4 + i) * SM_STRIDE + kk];
#pragma unroll
            for (int j = 0; j < 4; j++) kv[j] = KVs[kk * SM_STRIDE + tx * 4 + j];
#pragma unroll
            for (int i = 0; i < 4; i++)
#pragma unroll
                for (int j = 0; j < 4; j++) O[i][j] = fmaf(p[i], kv[j], O[i][j]);
        }
    }

    // Epilogue: divide by l, store to [B,S,H*Dk]
#pragma unroll
    for (int i = 0; i < 4; i++) {
        int r = ty * 4 + i;
        float inv = 1.f / l_sm[r];
#pragma unroll
        for (int j = 0; j < 4; j++) {
            int d = tx * 4 + j;
            C[((size_t)b * S_LEN + qbase + r) * DMODEL + h * DK + d] = O[i][j] * inv;
        }
    }
}

// =====================================================================
// Launch
// =====================================================================
extern "C" void kernel_launch(void* const* d_in, const int* in_sizes, int n_in,
                              void* d_out, int out_size)
{
    const float* value = (const float*)d_in[0];
    const float* key   = (const float*)d_in[1];
    const float* query = (const float*)d_in[2];
    const int*   mask  = (const int*)  d_in[3];
    const float* Wv = (const float*)d_in[4];
    const float* bv = (const float*)d_in[5];
    const float* Wk = (const float*)d_in[6];
    const float* bk = (const float*)d_in[7];
    const float* Wq = (const float*)d_in[8];
    const float* bq = (const float*)d_in[9];
    const float* Wo = (const float*)d_in[10];
    const float* bo = (const float*)d_in[11];
    float* out = (float*)d_out;

    float *qp, *vp, *kp, *att;
    cudaGetSymbolAddress((void**)&qp,  g_qp);
    cudaGetSymbolAddress((void**)&vp,  g_vp);
    cudaGetSymbolAddress((void**)&kp,  g_kp);
    cudaGetSymbolAddress((void**)&att, g_att);

    cudaFuncSetAttribute(attn_kernel, cudaFuncAttributeMaxDynamicSharedMemorySize,
                         ATTN_SMEM_BYTES);

    dim3 gblk(256);
    dim3 ggrid(DMODEL / BN, MROWS / BM);   // (8, 32)

    // Projections (note: q uses Wq/bq, etc.), output in [B,H,S,Dk]
    gemm_bias_kernel<<<ggrid, gblk>>>(query, Wq, bq, qp, MROWS, DMODEL, DMODEL, 1);
    gemm_bias_kernel<<<ggrid, gblk>>>(value, Wv, bv, vp, MROWS, DMODEL, DMODEL, 1);
    gemm_bias_kernel<<<ggrid, gblk>>>(key,   Wk, bk, kp, MROWS, DMODEL, DMODEL, 1);

    // Attention with reference's swapped K/V: scores vs Vproj, output vs Kproj
    dim3 agrid(S_LEN / AT_Q, NHEADS, BATCH);  // (32, 16, 2)
    attn_kernel<<<agrid, 256, ATTN_SMEM_BYTES>>>(qp, vp, kp, mask, att);

    // Output projection -> d_out [B*S, D]
    gemm_bias_kernel<<<ggrid, gblk>>>(att, Wo, bo, out, MROWS, DMODEL, DMODEL, 0);
}

// round 3
// speedup vs baseline: 2.3637x; 2.3637x over previous
#include <cuda_runtime.h>
#include <cstdint>
#include <math.h>

// Problem constants
#define S_LEN   2048
#define NHEADS  16
#define DK      64
#define DMODEL  1024
#define BATCH   2
#define MROWS   (BATCH * S_LEN)   // 4096

// ---------------- scratch (device globals; no allocation) ----------------
__device__ float g_qp[BATCH * NHEADS * S_LEN * DK];   // projected Q  [B,H,S,Dk]
__device__ float g_vp[BATCH * NHEADS * S_LEN * DK];   // projected V  [B,H,S,Dk]
__device__ float g_kp[BATCH * NHEADS * S_LEN * DK];   // projected K  [B,H,S,Dk]
__device__ float g_att[MROWS * DMODEL];               // attention out [B,S,D]

// ---------------- mma.sync helpers (tf32, m16n8k8) ----------------
__device__ __forceinline__ uint32_t f2tf32(float x) {
    uint32_t r;
    asm("cvt.rna.tf32.f32 %0, %1;" : "=r"(r) : "f"(x));
    return r;
}

__device__ __forceinline__ void mma_tf32(float d[4], const uint32_t a[4],
                                         const uint32_t b[2], const float c[4]) {
    asm volatile(
        "mma.sync.aligned.m16n8k8.row.col.f32.tf32.tf32.f32 "
        "{%0,%1,%2,%3}, {%4,%5,%6,%7}, {%8,%9}, {%10,%11,%12,%13};\n"
        : "=f"(d[0]), "=f"(d[1]), "=f"(d[2]), "=f"(d[3])
        : "r"(a[0]), "r"(a[1]), "r"(a[2]), "r"(a[3]),
          "r"(b[0]), "r"(b[1]),
          "f"(c[0]), "f"(c[1]), "f"(c[2]), "f"(c[3]));
}

// =====================================================================
// GEMM: C[m,n] = sum_k A[m,k]*W[n,k] + bias[n]   (x @ W^T + b)
// Block 128x128, BK=32, 256 threads (8 warps in 2x4), warp tile 64x32.
// =====================================================================
#define GASTR 132   // smem row stride (floats) for [32][128] tiles, pad 4

__global__ __launch_bounds__(256, 1) void gemm_mma_kernel(
    const float* __restrict__ A,     // [M, 1024]
    const float* __restrict__ W,     // [1024, 1024]
    const float* __restrict__ bias,  // [1024]
    float* __restrict__ C,
    int headSplit)
{
    __shared__ uint32_t As[32 * GASTR];
    __shared__ uint32_t Bs[32 * GASTR];

    const int tid  = threadIdx.x;
    const int lane = tid & 31;
    const int wid  = tid >> 5;
    const int warpM = wid & 1;       // 0..1
    const int warpN = wid >> 1;      // 0..3
    const int q  = lane & 3;
    const int rg = lane >> 2;
    const int blockRow = blockIdx.y * 128;
    const int blockCol = blockIdx.x * 128;

    float acc[4][4][4];
#pragma unroll
    for (int mt = 0; mt < 4; mt++)
#pragma unroll
        for (int nt = 0; nt < 4; nt++)
#pragma unroll
            for (int r = 0; r < 4; r++) acc[mt][nt][r] = 0.f;

    const int prow = tid >> 3;       // 0..31? no: tid>>3 = 0..31 for idx<256
    const int pc4  = tid & 7;

    float4 pa[4], pb[4];
    // initial prefetch (k0 = 0)
#pragma unroll
    for (int i = 0; i < 4; i++) {
        int row = prow + i * 32;     // (tid + i*256) >> 3
        pa[i] = *(const float4*)(A + (size_t)(blockRow + row) * DMODEL + pc4 * 4);
        pb[i] = *(const float4*)(W + (size_t)(blockCol + row) * DMODEL + pc4 * 4);
    }

    for (int kt = 0; kt < DMODEL / 32; kt++) {
        __syncthreads();
        // store prefetched tiles transposed into smem (tf32)
#pragma unroll
        for (int i = 0; i < 4; i++) {
            int row = prow + i * 32;
            As[(pc4 * 4 + 0) * GASTR + row] = f2tf32(pa[i].x);
            As[(pc4 * 4 + 1) * GASTR + row] = f2tf32(pa[i].y);
            As[(pc4 * 4 + 2) * GASTR + row] = f2tf32(pa[i].z);
            As[(pc4 * 4 + 3) * GASTR + row] = f2tf32(pa[i].w);
            Bs[(pc4 * 4 + 0) * GASTR + row] = f2tf32(pb[i].x);
            Bs[(pc4 * 4 + 1) * GASTR + row] = f2tf32(pb[i].y);
            Bs[(pc4 * 4 + 2) * GASTR + row] = f2tf32(pb[i].z);
            Bs[(pc4 * 4 + 3) * GASTR + row] = f2tf32(pb[i].w);
        }
        __syncthreads();

        // prefetch next chunk while computing this one
        if (kt + 1 < DMODEL / 32) {
            int k0 = (kt + 1) * 32;
#pragma unroll
            for (int i = 0; i < 4; i++) {
                int row = prow + i * 32;
                pa[i] = *(const float4*)(A + (size_t)(blockRow + row) * DMODEL + k0 + pc4 * 4);
                pb[i] = *(const float4*)(W + (size_t)(blockCol + row) * DMODEL + k0 + pc4 * 4);
            }
        }

#pragma unroll
        for (int kk = 0; kk < 4; kk++) {
            uint32_t af[4][4], bf[4][2];
#pragma unroll
            for (int mt = 0; mt < 4; mt++) {
                int m = warpM * 64 + mt * 16 + rg;
                af[mt][0] = As[(kk * 8 + q) * GASTR + m];
                af[mt][1] = As[(kk * 8 + q) * GASTR + m + 8];
                af[mt][2] = As[(kk * 8 + q + 4) * GASTR + m];
                af[mt][3] = As[(kk * 8 + q + 4) * GASTR + m + 8];
            }
#pragma unroll
            for (int nt = 0; nt < 4; nt++) {
                int n = warpN * 32 + nt * 8 + rg;
                bf[nt][0] = Bs[(kk * 8 + q) * GASTR + n];
                bf[nt][1] = Bs[(kk * 8 + q + 4) * GASTR + n];
            }
#pragma unroll
            for (int mt = 0; mt < 4; mt++)
#pragma unroll
                for (int nt = 0; nt < 4; nt++)
                    mma_tf32(acc[mt][nt], af[mt], bf[nt], acc[mt][nt]);
        }
    }

    // epilogue: bias + (optional head-split) store, float2 per reg-pair
#pragma unroll
    for (int mt = 0; mt < 4; mt++) {
        int m0 = blockRow + warpM * 64 + mt * 16 + rg;
        int m1 = m0 + 8;
#pragma unroll
        for (int nt = 0; nt < 4; nt++) {
            int n = blockCol + warpN * 32 + nt * 8 + 2 * q;
            float bx = __ldg(bias + n);
            float by = __ldg(bias + n + 1);
            float2 v0 = make_float2(acc[mt][nt][0] + bx, acc[mt][nt][1] + by);
            float2 v1 = make_float2(acc[mt][nt][2] + bx, acc[mt][nt][3] + by);
            if (headSplit) {
                int h = n >> 6, d = n & 63;
                *(float2*)&C[(((size_t)(m0 >> 11) * NHEADS + h) * S_LEN + (m0 & 2047)) * DK + d] = v0;
                *(float2*)&C[(((size_t)(m1 >> 11) * NHEADS + h) * S_LEN + (m1 & 2047)) * DK + d] = v1;
            } else {
                *(float2*)&C[(size_t)m0 * DMODEL + n] = v0;
                *(float2*)&C[(size_t)m1 * DMODEL + n] = v1;
            }
        }
    }
}

// =====================================================================
// Attention with the reference's K/V swap, tensorized:
//   S = Q @ Vproj^T * scale ; mask==0 -> -1e9 ; online softmax ; O += P @ Kproj
// 128 q-rows per CTA, 256 threads (8 warps; warp w owns q-rows 16w..16w+15).
// =====================================================================
#define VSTR 68
#define KSTR 72
#define PSTR 68
#define ATTN_SMEM_BYTES ((64 * VSTR + 64 * KSTR + 128 * PSTR) * 4)   // 70656

__global__ __launch_bounds__(256, 1) void attn_mma_kernel(
    const float* __restrict__ qp,   // [B,H,S,Dk] projected query
    const float* __restrict__ sp,   // [B,H,S,Dk] score keys (= projected VALUE)
    const float* __restrict__ op,   // [B,H,S,Dk] out values (= projected KEY)
    const int*   __restrict__ mask, // [B,S,S]
    float* __restrict__ C)          // [B,S,DMODEL]
{
    extern __shared__ uint32_t dsm[];
    uint32_t* Vs = dsm;                           // [64][VSTR]
    uint32_t* Ks = dsm + 64 * VSTR;               // [64][KSTR]
    uint32_t* Ps = dsm + 64 * VSTR + 64 * KSTR;   // [128][PSTR]

    const int tid  = threadIdx.x;
    const int lane = tid & 31;
    const int wid  = tid >> 5;
    const int q  = lane & 3;
    const int rg = lane >> 2;
    const int h  = blockIdx.y;
    const int b  = blockIdx.z;
    const int qbase = blockIdx.x * 128;
    const float scale = 0.125f;

    const float* qpb = qp + (((size_t)b * NHEADS + h) * S_LEN) * DK;
    const float* spb = sp + (((size_t)b * NHEADS + h) * S_LEN) * DK;
    const float* opb = op + (((size_t)b * NHEADS + h) * S_LEN) * DK;
    const int*   mbase = mask + (size_t)b * S_LEN * S_LEN;

    const int r0 = qbase + wid * 16 + rg;  // global q row for regs 0,1
    const int r1 = r0 + 8;                 // for regs 2,3
    const int lrow = wid * 16 + rg;

    // Q fragments, register-resident for the whole kv loop
    uint32_t qa[8][4];
#pragma unroll
    for (int dt = 0; dt < 8; dt++) {
        qa[dt][0] = f2tf32(__ldg(qpb + (size_t)r0 * DK + dt * 8 + q));
        qa[dt][1] = f2tf32(__ldg(qpb + (size_t)r1 * DK + dt * 8 + q));
        qa[dt][2] = f2tf32(__ldg(qpb + (size_t)r0 * DK + dt * 8 + q + 4));
        qa[dt][3] = f2tf32(__ldg(qpb + (size_t)r1 * DK + dt * 8 + q + 4));
    }

    float O[8][4];
#pragma unroll
    for (int nt = 0; nt < 8; nt++)
#pragma unroll
        for (int r = 0; r < 4; r++) O[nt][r] = 0.f;
    float m0 = -INFINITY, m1 = -INFINITY, l0 = 0.f, l1 = 0.f;

    for (int kt = 0; kt < S_LEN / 64; kt++) {
        const int kbase = kt * 64;
        __syncthreads();   // previous V/K tiles fully consumed

        // cooperative load of V and K tiles (64x64 each), tf32-converted
#pragma unroll
        for (int i = 0; i < 4; i++) {
            int idx = tid + i * 256;       // 0..1023
            int row = idx >> 4;
            int c4  = (idx & 15) * 4;
            float4 v = *(const float4*)(spb + (size_t)(kbase + row) * DK + c4);
            uint4 t;
            t.x = f2tf32(v.x); t.y = f2tf32(v.y); t.z = f2tf32(v.z); t.w = f2tf32(v.w);
            *(uint4*)&Vs[row * VSTR + c4] = t;
            float4 k4 = *(const float4*)(opb + (size_t)(kbase + row) * DK + c4);
            uint4 t2;
            t2.x = f2tf32(k4.x); t2.y = f2tf32(k4.y); t2.z = f2tf32(k4.z); t2.w = f2tf32(k4.w);
            *(uint4*)&Ks[row * KSTR + c4] = t2;
        }
        __syncthreads();

        // Stage 1: S = Q @ V^T   (per warp: 16 x 64)
        float s[8][4];
#pragma unroll
        for (int nt = 0; nt < 8; nt++)
#pragma unroll
            for (int r = 0; r < 4; r++) s[nt][r] = 0.f;

#pragma unroll
        for (int dt = 0; dt < 8; dt++) {
#pragma unroll
            for (int nt = 0; nt < 8; nt++) {
                uint32_t bf[2];
                bf[0] = Vs[(nt * 8 + rg) * VSTR + dt * 8 + q];
                bf[1] = Vs[(nt * 8 + rg) * VSTR + dt * 8 + q + 4];
                mma_tf32(s[nt], qa[dt], bf, s[nt]);
            }
        }

        // mask + scale + row max
        const int* mrow0 = mbase + (size_t)r0 * S_LEN + kbase;
        const int* mrow1 = mbase + (size_t)r1 * S_LEN + kbase;
        float mx0 = -INFINITY, mx1 = -INFINITY;
#pragma unroll
        for (int nt = 0; nt < 8; nt++) {
            int c = nt * 8 + 2 * q;
            s[nt][0] = __ldg(mrow0 + c)     ? s[nt][0] * scale : -1e9f;
            s[nt][1] = __ldg(mrow0 + c + 1) ? s[nt][1] * scale : -1e9f;
            s[nt][2] = __ldg(mrow1 + c)     ? s[nt][2] * scale : -1e9f;
            s[nt][3] = __ldg(mrow1 + c + 1) ? s[nt][3] * scale : -1e9f;
            mx0 = fmaxf(mx0, fmaxf(s[nt][0], s[nt][1]));
            mx1 = fmaxf(mx1, fmaxf(s[nt][2], s[nt][3]));
        }
        mx0 = fmaxf(mx0, __shfl_xor_sync(0xffffffffu, mx0, 1));
        mx0 = fmaxf(mx0, __shfl_xor_sync(0xffffffffu, mx0, 2));
        mx1 = fmaxf(mx1, __shfl_xor_sync(0xffffffffu, mx1, 1));
        mx1 = fmaxf(mx1, __shfl_xor_sync(0xffffffffu, mx1, 2));

        float mn0 = fmaxf(m0, mx0), mn1 = fmaxf(m1, mx1);
        float corr0 = __expf(m0 - mn0), corr1 = __expf(m1 - mn1);
        float sum0 = 0.f, sum1 = 0.f;
#pragma unroll
        for (int nt = 0; nt < 8; nt++) {
            s[nt][0] = __expf(s[nt][0] - mn0);
            s[nt][1] = __expf(s[nt][1] - mn0);
            s[nt][2] = __expf(s[nt][2] - mn1);
            s[nt][3] = __expf(s[nt][3] - mn1);
            sum0 += s[nt][0] + s[nt][1];
            sum1 += s[nt][2] + s[nt][3];
            uint2 p0 = make_uint2(f2tf32(s[nt][0]), f2tf32(s[nt][1]));
            uint2 p1 = make_uint2(f2tf32(s[nt][2]), f2tf32(s[nt][3]));
            *(uint2*)&Ps[(size_t)lrow * PSTR + nt * 8 + 2 * q] = p0;
            *(uint2*)&Ps[(size_t)(lrow + 8) * PSTR + nt * 8 + 2 * q] = p1;
        }
        sum0 += __shfl_xor_sync(0xffffffffu, sum0, 1);
        sum0 += __shfl_xor_sync(0xffffffffu, sum0, 2);
        sum1 += __shfl_xor_sync(0xffffffffu, sum1, 1);
        sum1 += __shfl_xor_sync(0xffffffffu, sum1, 2);
        l0 = l0 * corr0 + sum0;
        l1 = l1 * corr1 + sum1;
        m0 = mn0; m1 = mn1;
        __syncwarp();   // P visible within warp (each warp reads only its own rows)

        // rescale O, then O += P @ K
#pragma unroll
        for (int nt = 0; nt < 8; nt++) {
            O[nt][0] *= corr0; O[nt][1] *= corr0;
            O[nt][2] *= corr1; O[nt][3] *= corr1;
        }
#pragma unroll
        for (int k8 = 0; k8 < 8; k8++) {
            uint32_t af[4];
            af[0] = Ps[(size_t)lrow * PSTR + k8 * 8 + q];
            af[1] = Ps[(size_t)(lrow + 8) * PSTR + k8 * 8 + q];
            af[2] = Ps[(size_t)lrow * PSTR + k8 * 8 + q + 4];
            af[3] = Ps[(size_t)(lrow + 8) * PSTR + k8 * 8 + q + 4];
#pragma unroll
            for (int nt = 0; nt < 8; nt++) {
                uint32_t bf[2];
                bf[0] = Ks[(k8 * 8 + q) * KSTR + nt * 8 + rg];
                bf[1] = Ks[(k8 * 8 + q + 4) * KSTR + nt * 8 + rg];
                mma_tf32(O[nt], af, bf, O[nt]);
            }
        }
    }

    // epilogue: normalize, store to [B,S,H*Dk]
    float inv0 = 1.f / l0, inv1 = 1.f / l1;
#pragma unroll
    for (int nt = 0; nt < 8; nt++) {
        int d = h * DK + nt * 8 + 2 * q;
        float2 v0 = make_float2(O[nt][0] * inv0, O[nt][1] * inv0);
        float2 v1 = make_float2(O[nt][2] * inv1, O[nt][3] * inv1);
        *(float2*)&C[((size_t)b * S_LEN + r0) * DMODEL + d] = v0;
        *(float2*)&C[((size_t)b * S_LEN + r1) * DMODEL + d] = v1;
    }
}

// =====================================================================
// Launch
// =====================================================================
extern "C" void kernel_launch(void* const* d_in, const int* in_sizes, int n_in,
                              void* d_out, int out_size)
{
    const float* value = (const float*)d_in[0];
    const float* key   = (const float*)d_in[1];
    const float* query = (const float*)d_in[2];
    const int*   mask  = (const int*)  d_in[3];
    const float* Wv = (const float*)d_in[4];
    const float* bv = (const float*)d_in[5];
    const float* Wk = (const float*)d_in[6];
    const float* bk = (const float*)d_in[7];
    const float* Wq = (const float*)d_in[8];
    const float* bq = (const float*)d_in[9];
    const float* Wo = (const float*)d_in[10];
    const float* bo = (const float*)d_in[11];
    float* out = (float*)d_out;

    float *qp, *vp, *kp, *att;
    cudaGetSymbolAddress((void**)&qp,  g_qp);
    cudaGetSymbolAddress((void**)&vp,  g_vp);
    cudaGetSymbolAddress((void**)&kp,  g_kp);
    cudaGetSymbolAddress((void**)&att, g_att);

    cudaFuncSetAttribute(attn_mma_kernel, cudaFuncAttributeMaxDynamicSharedMemorySize,
                         ATTN_SMEM_BYTES);

    dim3 ggrid(DMODEL / 128, MROWS / 128);   // (8, 32)

    gemm_mma_kernel<<<ggrid, 256>>>(query, Wq, bq, qp, 1);
    gemm_mma_kernel<<<ggrid, 256>>>(value, Wv, bv, vp, 1);
    gemm_mma_kernel<<<ggrid, 256>>>(key,   Wk, bk, kp, 1);

    dim3 agrid(S_LEN / 128, NHEADS, BATCH);  // (16, 16, 2)
    attn_mma_kernel<<<agrid, 256, ATTN_SMEM_BYTES>>>(qp, vp, kp, mask, att);

    gemm_mma_kernel<<<ggrid, 256>>>(att, Wo, bo, out, 0);
}

// round 4
// speedup vs baseline: 6.7524x; 2.8567x over previous
#include <cuda_runtime.h>
#include <cuda_fp16.h>
#include <cstdint>
#include <math.h>

#define S_LEN   2048
#define NHEADS  16
#define DK      64
#define DMODEL  1024
#define BATCH   2
#define MROWS   (BATCH * S_LEN)   // 4096

// ---------------- scratch (device globals; no allocation) ----------------
__device__ __align__(16) __half g_hq [MROWS * DMODEL];
__device__ __align__(16) __half g_hk [MROWS * DMODEL];
__device__ __align__(16) __half g_hv [MROWS * DMODEL];
__device__ __align__(16) __half g_hwq[DMODEL * DMODEL];
__device__ __align__(16) __half g_hwk[DMODEL * DMODEL];
__device__ __align__(16) __half g_hwv[DMODEL * DMODEL];
__device__ __align__(16) __half g_hwo[DMODEL * DMODEL];
__device__ __align__(16) __half g_qp [MROWS * DMODEL];   // [B,H,S,DK]
__device__ __align__(16) __half g_vp [MROWS * DMODEL];
__device__ __align__(16) __half g_kp [MROWS * DMODEL];
__device__ __align__(16) __half g_att[MROWS * DMODEL];   // [B,S,D]
__device__ __align__(16) uint32_t g_mb[MROWS * (S_LEN / 32)];   // mask bitpack

// ---------------- asm helpers ----------------
__device__ __forceinline__ uint32_t smem_u32(const void* p) {
    uint32_t a;
    asm("{ .reg .u64 t; cvta.to.shared.u64 t, %1; cvt.u32.u64 %0, t; }" : "=r"(a) : "l"(p));
    return a;
}
#define CP_ASYNC16(dst, src) \
    asm volatile("cp.async.cg.shared.global [%0], [%1], 16;\n" :: "r"(dst), "l"(src))
#define CP_COMMIT() asm volatile("cp.async.commit_group;\n" ::: "memory")
#define CP_WAIT(n)  asm volatile("cp.async.wait_group %0;\n" :: "n"(n) : "memory")

__device__ __forceinline__ void mma_f16(float d[4], const uint32_t a[4],
                                        const uint32_t b[2], const float c[4]) {
    asm volatile(
        "mma.sync.aligned.m16n8k16.row.col.f32.f16.f16.f32 "
        "{%0,%1,%2,%3}, {%4,%5,%6,%7}, {%8,%9}, {%10,%11,%12,%13};\n"
        : "=f"(d[0]), "=f"(d[1]), "=f"(d[2]), "=f"(d[3])
        : "r"(a[0]), "r"(a[1]), "r"(a[2]), "r"(a[3]),
          "r"(b[0]), "r"(b[1]),
          "f"(c[0]), "f"(c[1]), "f"(c[2]), "f"(c[3]));
}

// =====================================================================
// Prepass 1: fp32 -> fp16 conversion (3 inputs @4M, 4 weights @1M)
// =====================================================================
__global__ void cvt_kernel(
    const float* s0, const float* s1, const float* s2,
    const float* s3, const float* s4, const float* s5, const float* s6,
    __half* d0, __half* d1, __half* d2,
    __half* d3, __half* d4, __half* d5, __half* d6)
{
    const float* s; __half* d; int n;
    switch (blockIdx.y) {
        case 0: s = s0; d = d0; n = MROWS * DMODEL; break;
        case 1: s = s1; d = d1; n = MROWS * DMODEL; break;
        case 2: s = s2; d = d2; n = MROWS * DMODEL; break;
        case 3: s = s3; d = d3; n = DMODEL * DMODEL; break;
        case 4: s = s4; d = d4; n = DMODEL * DMODEL; break;
        case 5: s = s5; d = d5; n = DMODEL * DMODEL; break;
        default: s = s6; d = d6; n = DMODEL * DMODEL; break;
    }
    int idx = (blockIdx.x * 256 + threadIdx.x) * 8;
    if (idx >= n) return;
    float4 a = *(const float4*)(s + idx);
    float4 b = *(const float4*)(s + idx + 4);
    __half2 h[4];
    h[0] = __floats2half2_rn(a.x, a.y);
    h[1] = __floats2half2_rn(a.z, a.w);
    h[2] = __floats2half2_rn(b.x, b.y);
    h[3] = __floats2half2_rn(b.z, b.w);
    *(uint4*)(d + idx) = *(uint4*)h;
}

// =====================================================================
// Prepass 2: mask [B,1,S,S] int32 -> bitmask [B*S][64] u32
// =====================================================================
__global__ void maskbits_kernel(const int* __restrict__ mask, uint32_t* __restrict__ mb)
{
    int row  = blockIdx.x * 8 + (threadIdx.x >> 5);   // 0..4095
    int lane = threadIdx.x & 31;
    const int* mrow = mask + (size_t)row * S_LEN;
    uint32_t* orow = mb + (size_t)row * (S_LEN / 32);
#pragma unroll 4
    for (int w = 0; w < S_LEN / 32; w++) {
        int v = mrow[w * 32 + lane];
        uint32_t bits = __ballot_sync(0xffffffffu, v != 0);
        if (lane == 0) orow[w] = bits;
    }
}

// =====================================================================
// fp16 GEMM: C[m,n] = sum_k A[m,k]*W[n,k] + bias[n]
// Block 128x128, BK=64, cp.async double-buffer, 8 warps (2x4), warp 64x32.
// =====================================================================
#define GKP   144                 // padded row: 72 halves = 144B
#define GTILE (128 * GKP)         // 18432 B
#define GEMM_SMEM_BYTES (4 * GTILE)   // 73728

__device__ __forceinline__ void gemm_body(
    const __half* __restrict__ A, const __half* __restrict__ W,
    const float* __restrict__ bias,
    __half* __restrict__ outH, float* __restrict__ outF, uint8_t* smem)
{
    const int tid = threadIdx.x;
    const int lane = tid & 31, wid = tid >> 5;
    const int warpM = wid & 1, warpN = wid >> 1;
    const int q = lane & 3, rg = lane >> 2;
    const int blockRow = blockIdx.y * 128;
    const int blockCol = blockIdx.x * 128;
    const uint32_t sb = smem_u32(smem);

    float acc[4][4][4];
#pragma unroll
    for (int mt = 0; mt < 4; mt++)
#pragma unroll
        for (int nt = 0; nt < 4; nt++)
#pragma unroll
            for (int r = 0; r < 4; r++) acc[mt][nt][r] = 0.f;

    const __half* Ab = A + (size_t)blockRow * DMODEL;
    const __half* Wb = W + (size_t)blockCol * DMODEL;

    const int crow = tid >> 3;      // chunk row base helper: (tid + i*256)>>3
    const int ccc  = tid & 7;

#define GEMM_ISSUE(st, kt) do {                                                   \
    const __half* As_ = Ab + (kt) * 64;                                           \
    const __half* Ws_ = Wb + (kt) * 64;                                           \
    _Pragma("unroll")                                                             \
    for (int i_ = 0; i_ < 4; i_++) {                                              \
        int row_ = crow + i_ * 32;                                                \
        CP_ASYNC16(sb + (st) * GTILE + row_ * GKP + ccc * 16,                     \
                   As_ + (size_t)row_ * DMODEL + ccc * 8);                        \
        CP_ASYNC16(sb + 2 * GTILE + (st) * GTILE + row_ * GKP + ccc * 16,         \
                   Ws_ + (size_t)row_ * DMODEL + ccc * 8);                        \
    }                                                                             \
} while (0)

    GEMM_ISSUE(0, 0);
    CP_COMMIT();

    for (int kt = 0; kt < DMODEL / 64; kt++) {
        if (kt < DMODEL / 64 - 1) {
            GEMM_ISSUE((kt + 1) & 1, kt + 1);
            CP_COMMIT();
            CP_WAIT(1);
        } else {
            CP_WAIT(0);
        }
        __syncthreads();

        const uint8_t* ab = smem + (kt & 1) * GTILE;
        const uint8_t* bb = smem + 2 * GTILE + (kt & 1) * GTILE;
#pragma unroll
        for (int kk = 0; kk < 4; kk++) {
            uint32_t af[4][4], bf[4][2];
#pragma unroll
            for (int mt = 0; mt < 4; mt++) {
                int m = warpM * 64 + mt * 16 + rg;
                const uint8_t* p = ab + m * GKP + (kk * 16 + 2 * q) * 2;
                af[mt][0] = *(const uint32_t*)(p);
                af[mt][1] = *(const uint32_t*)(p + 8 * GKP);
                af[mt][2] = *(const uint32_t*)(p + 16);
                af[mt][3] = *(const uint32_t*)(p + 8 * GKP + 16);
            }
#pragma unroll
            for (int nt = 0; nt < 4; nt++) {
                int n = warpN * 32 + nt * 8 + rg;
                const uint8_t* p = bb + n * GKP + (kk * 16 + 2 * q) * 2;
                bf[nt][0] = *(const uint32_t*)(p);
                bf[nt][1] = *(const uint32_t*)(p + 16);
            }
#pragma unroll
            for (int mt = 0; mt < 4; mt++)
#pragma unroll
                for (int nt = 0; nt < 4; nt++)
                    mma_f16(acc[mt][nt], af[mt], bf[nt], acc[mt][nt]);
        }
        __syncthreads();
    }

    // epilogue
#pragma unroll
    for (int mt = 0; mt < 4; mt++) {
        int m0 = blockRow + warpM * 64 + mt * 16 + rg;
        int m1 = m0 + 8;
#pragma unroll
        for (int nt = 0; nt < 4; nt++) {
            int n = blockCol + warpN * 32 + nt * 8 + 2 * q;
            float bx = __ldg(bias + n);
            float by = __ldg(bias + n + 1);
            float x0 = acc[mt][nt][0] + bx, y0 = acc[mt][nt][1] + by;
            float x1 = acc[mt][nt][2] + bx, y1 = acc[mt][nt][3] + by;
            if (outH) {     // head-split fp16 store [B,H,S,DK]
                int h = n >> 6, d = n & 63;
                size_t o0 = (((size_t)(m0 >> 11) * NHEADS + h) * S_LEN + (m0 & 2047)) * DK + d;
                size_t o1 = (((size_t)(m1 >> 11) * NHEADS + h) * S_LEN + (m1 & 2047)) * DK + d;
                *(__half2*)(outH + o0) = __floats2half2_rn(x0, y0);
                *(__half2*)(outH + o1) = __floats2half2_rn(x1, y1);
            } else {        // flat fp32 store
                *(float2*)&outF[(size_t)m0 * DMODEL + n] = make_float2(x0, y0);
                *(float2*)&outF[(size_t)m1 * DMODEL + n] = make_float2(x1, y1);
            }
        }
    }
}

__global__ __launch_bounds__(256, 2) void proj_gemm_kernel(
    const __half* xq, const __half* xv, const __half* xk,
    const __half* wq, const __half* wv, const __half* wk,
    const float* bq, const float* bv, const float* bk,
    __half* oq, __half* ov, __half* ok)
{
    extern __shared__ uint8_t gsm[];
    const __half *A, *W; const float* b; __half* o;
    if (blockIdx.z == 0)      { A = xq; W = wq; b = bq; o = oq; }
    else if (blockIdx.z == 1) { A = xv; W = wv; b = bv; o = ov; }
    else                      { A = xk; W = wk; b = bk; o = ok; }
    gemm_body(A, W, b, o, nullptr, gsm);
}

__global__ __launch_bounds__(256, 2) void out_gemm_kernel(
    const __half* A, const __half* W, const float* b, float* o)
{
    extern __shared__ uint8_t gsm[];
    gemm_body(A, W, b, nullptr, o, gsm);
}

// =====================================================================
// Attention (reference's K/V swap): S = Q@Vp^T*scale; mask; softmax; O += P@Kp
// 128 q-rows/CTA, 8 warps x 16 rows, fp16 mma m16n8k16, cp.async KV pipeline.
// =====================================================================
#define AKP     144                       // padded KV/P row: 72 halves
#define VBYTES  (64 * AKP)                // 9216
#define KVSTAGE (2 * VBYTES)              // V + K per stage
#define PS_OFF  (2 * KVSTAGE)             // 36864
#define ATTN_SMEM_BYTES (PS_OFF + 128 * AKP)   // 55296

__global__ __launch_bounds__(256, 2) void attn_kernel(
    const __half* __restrict__ qp,
    const __half* __restrict__ sp,   // score keys (= projected VALUE)
    const __half* __restrict__ op,   // out values (= projected KEY)
    const uint32_t* __restrict__ mb, // mask bitpack [B*S][64]
    __half* __restrict__ C)          // [B,S,D] fp16
{
    extern __shared__ uint8_t smem[];
    const uint32_t sb = smem_u32(smem);

    const int tid = threadIdx.x;
    const int lane = tid & 31, wid = tid >> 5;
    const int q = lane & 3, rg = lane >> 2;
    const int h = blockIdx.y, b = blockIdx.z;
    const int qbase = blockIdx.x * 128;
    const float scale = 0.125f;

    const __half* qpb = qp + (((size_t)b * NHEADS + h) * S_LEN) * DK;
    const __half* spb = sp + (((size_t)b * NHEADS + h) * S_LEN) * DK;
    const __half* opb = op + (((size_t)b * NHEADS + h) * S_LEN) * DK;
    const uint32_t* mbb = mb + ((size_t)b * S_LEN) * (S_LEN / 32);

    const int r0 = qbase + wid * 16 + rg;
    const int r1 = r0 + 8;
    const int lrow = wid * 16 + rg;

    // Q fragments (register-resident, fp16)
    uint32_t qa[4][4];
    {
        const __half* q0 = qpb + (size_t)r0 * DK;
        const __half* q1 = qpb + (size_t)r1 * DK;
#pragma unroll
        for (int dt = 0; dt < 4; dt++) {
            qa[dt][0] = *(const uint32_t*)(q0 + dt * 16 + 2 * q);
            qa[dt][1] = *(const uint32_t*)(q1 + dt * 16 + 2 * q);
            qa[dt][2] = *(const uint32_t*)(q0 + dt * 16 + 2 * q + 8);
            qa[dt][3] = *(const uint32_t*)(q1 + dt * 16 + 2 * q + 8);
        }
    }

    float O[8][4];
#pragma unroll
    for (int nt = 0; nt < 8; nt++)
#pragma unroll
        for (int r = 0; r < 4; r++) O[nt][r] = 0.f;
    float m0 = -INFINITY, m1 = -INFINITY, l0 = 0.f, l1 = 0.f;

    const int crow = tid >> 3;
    const int ccc  = tid & 7;
#define ATTN_ISSUE(st, kt) do {                                                    \
    const __half* vs_ = spb + (size_t)(kt) * 64 * DK;                              \
    const __half* ks_ = opb + (size_t)(kt) * 64 * DK;                              \
    _Pragma("unroll")                                                              \
    for (int i_ = 0; i_ < 2; i_++) {                                               \
        int row_ = crow + i_ * 32;                                                 \
        CP_ASYNC16(sb + (st) * KVSTAGE + row_ * AKP + ccc * 16,                    \
                   vs_ + (size_t)row_ * DK + ccc * 8);                             \
        CP_ASYNC16(sb + (st) * KVSTAGE + VBYTES + row_ * AKP + ccc * 16,           \
                   ks_ + (size_t)row_ * DK + ccc * 8);                             \
    }                                                                              \
} while (0)

    ATTN_ISSUE(0, 0);
    CP_COMMIT();

    for (int kt = 0; kt < S_LEN / 64; kt++) {
        if (kt < S_LEN / 64 - 1) {
            ATTN_ISSUE((kt + 1) & 1, kt + 1);
            CP_COMMIT();
            CP_WAIT(1);
        } else {
            CP_WAIT(0);
        }
        __syncthreads();

        const uint8_t* vsb = smem + (kt & 1) * KVSTAGE;
        const uint32_t ksb = sb + (kt & 1) * KVSTAGE + VBYTES;

        // ---- S = Q @ V^T ----
        float s[8][4];
#pragma unroll
        for (int nt = 0; nt < 8; nt++)
#pragma unroll
            for (int r = 0; r < 4; r++) s[nt][r] = 0.f;
#pragma unroll
        for (int dt = 0; dt < 4; dt++)
#pragma unroll
            for (int nt = 0; nt < 8; nt++) {
                const uint8_t* p = vsb + (nt * 8 + rg) * AKP + (dt * 16 + 2 * q) * 2;
                uint32_t bf[2];
                bf[0] = *(const uint32_t*)(p);
                bf[1] = *(const uint32_t*)(p + 16);
                mma_f16(s[nt], qa[dt], bf, s[nt]);
            }

        // ---- mask (bitpacked) + scale + online softmax ----
        uint64_t mk0, mk1;
        {
            const uint32_t* w0 = mbb + (size_t)r0 * 64 + kt * 2;
            const uint32_t* w1 = mbb + (size_t)r1 * 64 + kt * 2;
            mk0 = (uint64_t)w0[0] | ((uint64_t)w0[1] << 32);
            mk1 = (uint64_t)w1[0] | ((uint64_t)w1[1] << 32);
        }
        float mx0 = -INFINITY, mx1 = -INFINITY;
#pragma unroll
        for (int nt = 0; nt < 8; nt++) {
            int c = nt * 8 + 2 * q;
            s[nt][0] = ((mk0 >> c) & 1)       ? s[nt][0] * scale : -1e9f;
            s[nt][1] = ((mk0 >> (c + 1)) & 1) ? s[nt][1] * scale : -1e9f;
            s[nt][2] = ((mk1 >> c) & 1)       ? s[nt][2] * scale : -1e9f;
            s[nt][3] = ((mk1 >> (c + 1)) & 1) ? s[nt][3] * scale : -1e9f;
            mx0 = fmaxf(mx0, fmaxf(s[nt][0], s[nt][1]));
            mx1 = fmaxf(mx1, fmaxf(s[nt][2], s[nt][3]));
        }
        mx0 = fmaxf(mx0, __shfl_xor_sync(0xffffffffu, mx0, 1));
        mx0 = fmaxf(mx0, __shfl_xor_sync(0xffffffffu, mx0, 2));
        mx1 = fmaxf(mx1, __shfl_xor_sync(0xffffffffu, mx1, 1));
        mx1 = fmaxf(mx1, __shfl_xor_sync(0xffffffffu, mx1, 2));

        float mn0 = fmaxf(m0, mx0), mn1 = fmaxf(m1, mx1);
        float corr0 = __expf(m0 - mn0), corr1 = __expf(m1 - mn1);
        float sum0 = 0.f, sum1 = 0.f;
        uint8_t* ps0 = smem + PS_OFF + lrow * AKP;
        uint8_t* ps1 = ps0 + 8 * AKP;
#pragma unroll
        for (int nt = 0; nt < 8; nt++) {
            s[nt][0] = __expf(s[nt][0] - mn0);
            s[nt][1] = __expf(s[nt][1] - mn0);
            s[nt][2] = __expf(s[nt][2] - mn1);
            s[nt][3] = __expf(s[nt][3] - mn1);
            sum0 += s[nt][0] + s[nt][1];
            sum1 += s[nt][2] + s[nt][3];
            *(__half2*)(ps0 + (nt * 8 + 2 * q) * 2) = __floats2half2_rn(s[nt][0], s[nt][1]);
            *(__half2*)(ps1 + (nt * 8 + 2 * q) * 2) = __floats2half2_rn(s[nt][2], s[nt][3]);
        }
        sum0 += __shfl_xor_sync(0xffffffffu, sum0, 1);
        sum0 += __shfl_xor_sync(0xffffffffu, sum0, 2);
        sum1 += __shfl_xor_sync(0xffffffffu, sum1, 1);
        sum1 += __shfl_xor_sync(0xffffffffu, sum1, 2);
        l0 = l0 * corr0 + sum0;
        l1 = l1 * corr1 + sum1;
        m0 = mn0; m1 = mn1;

        // ---- O = O*corr + P @ K ----
#pragma unroll
        for (int nt = 0; nt < 8; nt++) {
            O[nt][0] *= corr0; O[nt][1] *= corr0;
            O[nt][2] *= corr1; O[nt][3] *= corr1;
        }
        __syncwarp();
#pragma unroll
        for (int dt2 = 0; dt2 < 4; dt2++) {
            uint32_t af[4];
            {
                const uint8_t* pa = smem + PS_OFF + lrow * AKP + (dt2 * 16 + 2 * q) * 2;
                af[0] = *(const uint32_t*)(pa);
                af[1] = *(const uint32_t*)(pa + 8 * AKP);
                af[2] = *(const uint32_t*)(pa + 16);
                af[3] = *(const uint32_t*)(pa + 8 * AKP + 16);
            }
            const int krow = dt2 * 16 + (lane & 7) + ((lane >> 3) & 1) * 8;
#pragma unroll
            for (int ntp = 0; ntp < 4; ntp++) {
                const int ncol = ntp * 16 + ((lane >> 4) & 1) * 8;
                uint32_t b0, b1, b2, b3;
                uint32_t addr = ksb + krow * AKP + ncol * 2;
                asm volatile(
                    "ldmatrix.sync.aligned.m8n8.x4.trans.shared.b16 {%0,%1,%2,%3}, [%4];"
                    : "=r"(b0), "=r"(b1), "=r"(b2), "=r"(b3) : "r"(addr));
                uint32_t bA[2] = {b0, b1}, bB[2] = {b2, b3};
                mma_f16(O[ntp * 2],     af, bA, O[ntp * 2]);
                mma_f16(O[ntp * 2 + 1], af, bB, O[ntp * 2 + 1]);
            }
        }
        __syncthreads();
    }

    // epilogue: normalize, fp16 store to [B,S,H*DK]
    float inv0 = 1.f / l0, inv1 = 1.f / l1;
    __half* c0 = C + ((size_t)b * S_LEN + r0) * DMODEL + h * DK;
    __half* c1 = C + ((size_t)b * S_LEN + r1) * DMODEL + h * DK;
#pragma unroll
    for (int nt = 0; nt < 8; nt++) {
        int d = nt * 8 + 2 * q;
        *(__half2*)(c0 + d) = __floats2half2_rn(O[nt][0] * inv0, O[nt][1] * inv0);
        *(__half2*)(c1 + d) = __floats2half2_rn(O[nt][2] * inv1, O[nt][3] * inv1);
    }
}

// =====================================================================
// Launch
// =====================================================================
extern "C" void kernel_launch(void* const* d_in, const int* in_sizes, int n_in,
                              void* d_out, int out_size)
{
    const float* value = (const float*)d_in[0];
    const float* key   = (const float*)d_in[1];
    const float* query = (const float*)d_in[2];
    const int*   mask  = (const int*)  d_in[3];
    const float* Wv = (const float*)d_in[4];
    const float* bv = (const float*)d_in[5];
    const float* Wk = (const float*)d_in[6];
    const float* bk = (const float*)d_in[7];
    const float* Wq = (const float*)d_in[8];
    const float* bq = (const float*)d_in[9];
    const float* Wo = (const float*)d_in[10];
    const float* bo = (const float*)d_in[11];
    float* out = (float*)d_out;

    __half *hq, *hk, *hv, *hwq, *hwk, *hwv, *hwo, *qp, *vp, *kp, *att;
    uint32_t* mb;
    cudaGetSymbolAddress((void**)&hq,  g_hq);
    cudaGetSymbolAddress((void**)&hk,  g_hk);
    cudaGetSymbolAddress((void**)&hv,  g_hv);
    cudaGetSymbolAddress((void**)&hwq, g_hwq);
    cudaGetSymbolAddress((void**)&hwk, g_hwk);
    cudaGetSymbolAddress((void**)&hwv, g_hwv);
    cudaGetSymbolAddress((void**)&hwo, g_hwo);
    cudaGetSymbolAddress((void**)&qp,  g_qp);
    cudaGetSymbolAddress((void**)&vp,  g_vp);
    cudaGetSymbolAddress((void**)&kp,  g_kp);
    cudaGetSymbolAddress((void**)&att, g_att);
    cudaGetSymbolAddress((void**)&mb,  g_mb);

    cudaFuncSetAttribute(proj_gemm_kernel, cudaFuncAttributeMaxDynamicSharedMemorySize,
                         GEMM_SMEM_BYTES);
    cudaFuncSetAttribute(out_gemm_kernel, cudaFuncAttributeMaxDynamicSharedMemorySize,
                         GEMM_SMEM_BYTES);
    cudaFuncSetAttribute(attn_kernel, cudaFuncAttributeMaxDynamicSharedMemorySize,
                         ATTN_SMEM_BYTES);

    // prepass: conversions + mask bitpack
    cvt_kernel<<<dim3(2048, 7), 256>>>(query, value, key, Wq, Wv, Wk, Wo,
                                       hq, hv, hk, hwq, hwv, hwk, hwo);
    maskbits_kernel<<<MROWS / 8, 256>>>(mask, mb);

    // fused 3 projections
    proj_gemm_kernel<<<dim3(8, 32, 3), 256, GEMM_SMEM_BYTES>>>(
        hq, hv, hk, hwq, hwv, hwk, bq, bv, bk, qp, vp, kp);

    // attention (swapped K/V per reference)
    attn_kernel<<<dim3(S_LEN / 128, NHEADS, BATCH), 256, ATTN_SMEM_BYTES>>>(
        qp, vp, kp, mb, att);

    // output projection
    out_gemm_kernel<<<dim3(8, 32), 256, GEMM_SMEM_BYTES>>>(att, hwo, bo, out);
}

// round 5
// speedup vs baseline: 7.2770x; 1.0777x over previous
#include <cuda_runtime.h>
#include <cuda_fp16.h>
#include <cstdint>
#include <math.h>

#define S_LEN   2048
#define NHEADS  16
#define DK      64
#define DMODEL  1024
#define BATCH   2
#define MROWS   (BATCH * S_LEN)   // 4096

// ---------------- scratch (device globals; no allocation) ----------------
__device__ __align__(16) __half g_hq [MROWS * DMODEL];
__device__ __align__(16) __half g_hk [MROWS * DMODEL];
__device__ __align__(16) __half g_hv [MROWS * DMODEL];
__device__ __align__(16) __half g_hwq[DMODEL * DMODEL];
__device__ __align__(16) __half g_hwk[DMODEL * DMODEL];
__device__ __align__(16) __half g_hwv[DMODEL * DMODEL];
__device__ __align__(16) __half g_hwo[DMODEL * DMODEL];
__device__ __align__(16) __half g_qp [MROWS * DMODEL];   // [B,H,S,DK]
__device__ __align__(16) __half g_vp [MROWS * DMODEL];
__device__ __align__(16) __half g_kp [MROWS * DMODEL];
__device__ __align__(16) __half g_att[MROWS * DMODEL];   // [B,S,D]
__device__ __align__(16) uint32_t g_mb[MROWS * (S_LEN / 32)];   // mask bitpack

// ---------------- asm helpers ----------------
__device__ __forceinline__ uint32_t smem_u32(const void* p) {
    uint32_t a;
    asm("{ .reg .u64 t; cvta.to.shared.u64 t, %1; cvt.u32.u64 %0, t; }" : "=r"(a) : "l"(p));
    return a;
}
#define CP_ASYNC16(dst, src) \
    asm volatile("cp.async.cg.shared.global [%0], [%1], 16;\n" :: "r"(dst), "l"(src))
#define CP_COMMIT() asm volatile("cp.async.commit_group;\n" ::: "memory")
#define CP_WAIT(n)  asm volatile("cp.async.wait_group %0;\n" :: "n"(n) : "memory")

__device__ __forceinline__ void mma_f16(float d[4], const uint32_t a[4],
                                        const uint32_t b[2], const float c[4]) {
    asm volatile(
        "mma.sync.aligned.m16n8k16.row.col.f32.f16.f16.f32 "
        "{%0,%1,%2,%3}, {%4,%5,%6,%7}, {%8,%9}, {%10,%11,%12,%13};\n"
        : "=f"(d[0]), "=f"(d[1]), "=f"(d[2]), "=f"(d[3])
        : "r"(a[0]), "r"(a[1]), "r"(a[2]), "r"(a[3]),
          "r"(b[0]), "r"(b[1]),
          "f"(c[0]), "f"(c[1]), "f"(c[2]), "f"(c[3]));
}
#define LDMX4(r0, r1, r2, r3, addr) \
    asm volatile("ldmatrix.sync.aligned.m8n8.x4.shared.b16 {%0,%1,%2,%3}, [%4];" \
        : "=r"(r0), "=r"(r1), "=r"(r2), "=r"(r3) : "r"(addr))
#define LDMX4T(r0, r1, r2, r3, addr) \
    asm volatile("ldmatrix.sync.aligned.m8n8.x4.trans.shared.b16 {%0,%1,%2,%3}, [%4];" \
        : "=r"(r0), "=r"(r1), "=r"(r2), "=r"(r3) : "r"(addr))

__device__ __forceinline__ uint32_t h2pack(float a, float b) {
    __half2 h = __floats2half2_rn(a, b);
    return *(uint32_t*)&h;
}

// =====================================================================
// Prepass 1: fp32 -> fp16 conversion (3 inputs @4M, 4 weights @1M)
// =====================================================================
__global__ void cvt_kernel(
    const float* s0, const float* s1, const float* s2,
    const float* s3, const float* s4, const float* s5, const float* s6,
    __half* d0, __half* d1, __half* d2,
    __half* d3, __half* d4, __half* d5, __half* d6)
{
    const float* s; __half* d; int n;
    switch (blockIdx.y) {
        case 0: s = s0; d = d0; n = MROWS * DMODEL; break;
        case 1: s = s1; d = d1; n = MROWS * DMODEL; break;
        case 2: s = s2; d = d2; n = MROWS * DMODEL; break;
        case 3: s = s3; d = d3; n = DMODEL * DMODEL; break;
        case 4: s = s4; d = d4; n = DMODEL * DMODEL; break;
        case 5: s = s5; d = d5; n = DMODEL * DMODEL; break;
        default: s = s6; d = d6; n = DMODEL * DMODEL; break;
    }
    int idx = (blockIdx.x * 256 + threadIdx.x) * 8;
    if (idx >= n) return;
    float4 a = *(const float4*)(s + idx);
    float4 b = *(const float4*)(s + idx + 4);
    __half2 h[4];
    h[0] = __floats2half2_rn(a.x, a.y);
    h[1] = __floats2half2_rn(a.z, a.w);
    h[2] = __floats2half2_rn(b.x, b.y);
    h[3] = __floats2half2_rn(b.z, b.w);
    *(uint4*)(d + idx) = *(uint4*)h;
}

// =====================================================================
// Prepass 2: mask [B,1,S,S] int32 -> bitmask [B*S][64] u32
// =====================================================================
__global__ void maskbits_kernel(const int* __restrict__ mask, uint32_t* __restrict__ mb)
{
    int row  = blockIdx.x * 8 + (threadIdx.x >> 5);
    int lane = threadIdx.x & 31;
    const int* mrow = mask + (size_t)row * S_LEN;
    uint32_t* orow = mb + (size_t)row * (S_LEN / 32);
#pragma unroll 4
    for (int w = 0; w < S_LEN / 32; w++) {
        int v = mrow[w * 32 + lane];
        uint32_t bits = __ballot_sync(0xffffffffu, v != 0);
        if (lane == 0) orow[w] = bits;
    }
}

// =====================================================================
// fp16 GEMM: C[m,n] = sum_k A[m,k]*W[n,k] + bias[n]
// Block 128x128, BK=64, cp.async double-buffer, 8 warps (2x4), warp 64x32.
// Fragment loads via ldmatrix.x4.
// =====================================================================
#define GKP   144
#define GTILE (128 * GKP)
#define GEMM_SMEM_BYTES (4 * GTILE)   // 73728

__device__ __forceinline__ void gemm_body(
    const __half* __restrict__ A, const __half* __restrict__ W,
    const float* __restrict__ bias,
    __half* __restrict__ outH, float* __restrict__ outF, uint8_t* smem)
{
    const int tid = threadIdx.x;
    const int lane = tid & 31, wid = tid >> 5;
    const int warpM = wid & 1, warpN = wid >> 1;
    const int q = lane & 3, rg = lane >> 2;
    const int blockRow = blockIdx.y * 128;
    const int blockCol = blockIdx.x * 128;
    const uint32_t sb = smem_u32(smem);

    // ldmatrix lane address components
    const int arow = (lane & 7) + ((lane >> 3) & 1) * 8;   // A: m1 = row+8
    const int acol = ((lane >> 4) & 1) * 8;                // A: m2/m3 = col+8
    const int brow = (lane & 7) + ((lane >> 4) & 1) * 8;   // B: m2/m3 = row+8
    const int bcol = ((lane >> 3) & 1) * 8;                // B: m1 = col+8

    float acc[4][4][4];
#pragma unroll
    for (int mt = 0; mt < 4; mt++)
#pragma unroll
        for (int nt = 0; nt < 4; nt++)
#pragma unroll
            for (int r = 0; r < 4; r++) acc[mt][nt][r] = 0.f;

    const __half* Ab = A + (size_t)blockRow * DMODEL;
    const __half* Wb = W + (size_t)blockCol * DMODEL;

    const int crow = tid >> 3;
    const int ccc  = tid & 7;

#define GEMM_ISSUE(st, kt) do {                                                   \
    const __half* As_ = Ab + (kt) * 64;                                           \
    const __half* Ws_ = Wb + (kt) * 64;                                           \
    _Pragma("unroll")                                                             \
    for (int i_ = 0; i_ < 4; i_++) {                                              \
        int row_ = crow + i_ * 32;                                                \
        CP_ASYNC16(sb + (st) * GTILE + row_ * GKP + ccc * 16,                     \
                   As_ + (size_t)row_ * DMODEL + ccc * 8);                        \
        CP_ASYNC16(sb + 2 * GTILE + (st) * GTILE + row_ * GKP + ccc * 16,         \
                   Ws_ + (size_t)row_ * DMODEL + ccc * 8);                        \
    }                                                                             \
} while (0)

    GEMM_ISSUE(0, 0);
    CP_COMMIT();

    for (int kt = 0; kt < DMODEL / 64; kt++) {
        if (kt < DMODEL / 64 - 1) {
            GEMM_ISSUE((kt + 1) & 1, kt + 1);
            CP_COMMIT();
            CP_WAIT(1);
        } else {
            CP_WAIT(0);
        }
        __syncthreads();

        const uint32_t abu = sb + (kt & 1) * GTILE;
        const uint32_t bbu = sb + 2 * GTILE + (kt & 1) * GTILE;
#pragma unroll
        for (int kk = 0; kk < 4; kk++) {
            uint32_t af[4][4], bf[4][2];
#pragma unroll
            for (int mt = 0; mt < 4; mt++) {
                uint32_t addr = abu + (warpM * 64 + mt * 16 + arow) * GKP
                              + (kk * 16 + acol) * 2;
                LDMX4(af[mt][0], af[mt][1], af[mt][2], af[mt][3], addr);
            }
#pragma unroll
            for (int np = 0; np < 2; np++) {
                uint32_t r0, r1, r2, r3;
                uint32_t addr = bbu + (warpN * 32 + np * 16 + brow) * GKP
                              + (kk * 16 + bcol) * 2;
                LDMX4(r0, r1, r2, r3, addr);
                bf[np * 2][0] = r0;     bf[np * 2][1] = r1;
                bf[np * 2 + 1][0] = r2; bf[np * 2 + 1][1] = r3;
            }
#pragma unroll
            for (int mt = 0; mt < 4; mt++)
#pragma unroll
                for (int nt = 0; nt < 4; nt++)
                    mma_f16(acc[mt][nt], af[mt], bf[nt], acc[mt][nt]);
        }
        __syncthreads();
    }

    // epilogue
#pragma unroll
    for (int mt = 0; mt < 4; mt++) {
        int m0 = blockRow + warpM * 64 + mt * 16 + rg;
        int m1 = m0 + 8;
#pragma unroll
        for (int nt = 0; nt < 4; nt++) {
            int n = blockCol + warpN * 32 + nt * 8 + 2 * q;
            float bx = __ldg(bias + n);
            float by = __ldg(bias + n + 1);
            float x0 = acc[mt][nt][0] + bx, y0 = acc[mt][nt][1] + by;
            float x1 = acc[mt][nt][2] + bx, y1 = acc[mt][nt][3] + by;
            if (outH) {
                int h = n >> 6, d = n & 63;
                size_t o0 = (((size_t)(m0 >> 11) * NHEADS + h) * S_LEN + (m0 & 2047)) * DK + d;
                size_t o1 = (((size_t)(m1 >> 11) * NHEADS + h) * S_LEN + (m1 & 2047)) * DK + d;
                *(__half2*)(outH + o0) = __floats2half2_rn(x0, y0);
                *(__half2*)(outH + o1) = __floats2half2_rn(x1, y1);
            } else {
                *(float2*)&outF[(size_t)m0 * DMODEL + n] = make_float2(x0, y0);
                *(float2*)&outF[(size_t)m1 * DMODEL + n] = make_float2(x1, y1);
            }
        }
    }
}

__global__ __launch_bounds__(256, 2) void proj_gemm_kernel(
    const __half* xq, const __half* xv, const __half* xk,
    const __half* wq, const __half* wv, const __half* wk,
    const float* bq, const float* bv, const float* bk,
    __half* oq, __half* ov, __half* ok)
{
    extern __shared__ uint8_t gsm[];
    const __half *A, *W; const float* b; __half* o;
    if (blockIdx.z == 0)      { A = xq; W = wq; b = bq; o = oq; }
    else if (blockIdx.z == 1) { A = xv; W = wv; b = bv; o = ov; }
    else                      { A = xk; W = wk; b = bk; o = ok; }
    gemm_body(A, W, b, o, nullptr, gsm);
}

__global__ __launch_bounds__(256, 2) void out_gemm_kernel(
    const __half* A, const __half* W, const float* b, float* o)
{
    extern __shared__ uint8_t gsm[];
    gemm_body(A, W, b, nullptr, o, gsm);
}

// =====================================================================
// Attention (reference's K/V swap): S = Q@Vp^T*scale; mask; softmax; O += P@Kp
// 128 q-rows/CTA, 8 warps x 16 rows. P kept in registers (C-frag -> A-frag).
// =====================================================================
#define AKP     144
#define VBYTES  (64 * AKP)                // 9216
#define KVSTAGE (2 * VBYTES)              // V + K per stage
#define ATTN_SMEM_BYTES (2 * KVSTAGE)     // 36864

__global__ __launch_bounds__(256, 2) void attn_kernel(
    const __half* __restrict__ qp,
    const __half* __restrict__ sp,   // score keys (= projected VALUE)
    const __half* __restrict__ op,   // out values (= projected KEY)
    const uint32_t* __restrict__ mb,
    __half* __restrict__ C)          // [B,S,D] fp16
{
    extern __shared__ uint8_t smem[];
    const uint32_t sb = smem_u32(smem);

    const int tid = threadIdx.x;
    const int lane = tid & 31, wid = tid >> 5;
    const int q = lane & 3, rg = lane >> 2;
    const int h = blockIdx.y, b = blockIdx.z;
    const int qbase = blockIdx.x * 128;
    const float scale = 0.125f;

    const __half* qpb = qp + (((size_t)b * NHEADS + h) * S_LEN) * DK;
    const __half* spb = sp + (((size_t)b * NHEADS + h) * S_LEN) * DK;
    const __half* opb = op + (((size_t)b * NHEADS + h) * S_LEN) * DK;
    const uint32_t* mbb = mb + ((size_t)b * S_LEN) * (S_LEN / 32);

    const int r0 = qbase + wid * 16 + rg;
    const int r1 = r0 + 8;

    // ldmatrix lane address components (B-operand style for V)
    const int brow = (lane & 7) + ((lane >> 4) & 1) * 8;
    const int bcol = ((lane >> 3) & 1) * 8;
    // for K ldmatrix.trans (same as R4)
    const int krowl = (lane & 7) + ((lane >> 3) & 1) * 8;
    const int kcoll = ((lane >> 4) & 1) * 8;

    // Q fragments (register-resident)
    uint32_t qa[4][4];
    {
        const __half* q0 = qpb + (size_t)r0 * DK;
        const __half* q1 = qpb + (size_t)r1 * DK;
#pragma unroll
        for (int dt = 0; dt < 4; dt++) {
            qa[dt][0] = *(const uint32_t*)(q0 + dt * 16 + 2 * q);
            qa[dt][1] = *(const uint32_t*)(q1 + dt * 16 + 2 * q);
            qa[dt][2] = *(const uint32_t*)(q0 + dt * 16 + 2 * q + 8);
            qa[dt][3] = *(const uint32_t*)(q1 + dt * 16 + 2 * q + 8);
        }
    }

    float O[8][4];
#pragma unroll
    for (int nt = 0; nt < 8; nt++)
#pragma unroll
        for (int r = 0; r < 4; r++) O[nt][r] = 0.f;
    float m0 = -INFINITY, m1 = -INFINITY, l0 = 0.f, l1 = 0.f;

    const int crow = tid >> 3;
    const int ccc  = tid & 7;
#define ATTN_ISSUE(st, kt) do {                                                    \
    const __half* vs_ = spb + (size_t)(kt) * 64 * DK;                              \
    const __half* ks_ = opb + (size_t)(kt) * 64 * DK;                              \
    _Pragma("unroll")                                                              \
    for (int i_ = 0; i_ < 2; i_++) {                                               \
        int row_ = crow + i_ * 32;                                                 \
        CP_ASYNC16(sb + (st) * KVSTAGE + row_ * AKP + ccc * 16,                    \
                   vs_ + (size_t)row_ * DK + ccc * 8);                             \
        CP_ASYNC16(sb + (st) * KVSTAGE + VBYTES + row_ * AKP + ccc * 16,           \
                   ks_ + (size_t)row_ * DK + ccc * 8);                             \
    }                                                                              \
} while (0)

    ATTN_ISSUE(0, 0);
    CP_COMMIT();

    for (int kt = 0; kt < S_LEN / 64; kt++) {
        if (kt < S_LEN / 64 - 1) {
            ATTN_ISSUE((kt + 1) & 1, kt + 1);
            CP_COMMIT();
            CP_WAIT(1);
        } else {
            CP_WAIT(0);
        }
        __syncthreads();

        const uint32_t vsb = sb + (kt & 1) * KVSTAGE;
        const uint32_t ksb = vsb + VBYTES;

        // ---- S = Q @ V^T (ldmatrix.x4 for V fragments) ----
        float s[8][4];
#pragma unroll
        for (int nt = 0; nt < 8; nt++)
#pragma unroll
            for (int r = 0; r < 4; r++) s[nt][r] = 0.f;
#pragma unroll
        for (int dt = 0; dt < 4; dt++) {
#pragma unroll
            for (int np = 0; np < 4; np++) {
                uint32_t v0, v1, v2, v3;
                uint32_t addr = vsb + (np * 16 + brow) * AKP + (dt * 16 + bcol) * 2;
                LDMX4(v0, v1, v2, v3, addr);
                uint32_t bA[2] = {v0, v1}, bB[2] = {v2, v3};
                mma_f16(s[np * 2],     qa[dt], bA, s[np * 2]);
                mma_f16(s[np * 2 + 1], qa[dt], bB, s[np * 2 + 1]);
            }
        }

        // ---- mask + scale + online softmax ----
        uint64_t mk0, mk1;
        {
            const uint32_t* w0 = mbb + (size_t)r0 * 64 + kt * 2;
            const uint32_t* w1 = mbb + (size_t)r1 * 64 + kt * 2;
            mk0 = (uint64_t)w0[0] | ((uint64_t)w0[1] << 32);
            mk1 = (uint64_t)w1[0] | ((uint64_t)w1[1] << 32);
        }
        float mx0 = -INFINITY, mx1 = -INFINITY;
#pragma unroll
        for (int nt = 0; nt < 8; nt++) {
            int c = nt * 8 + 2 * q;
            s[nt][0] = ((mk0 >> c) & 1)       ? s[nt][0] * scale : -1e9f;
            s[nt][1] = ((mk0 >> (c + 1)) & 1) ? s[nt][1] * scale : -1e9f;
            s[nt][2] = ((mk1 >> c) & 1)       ? s[nt][2] * scale : -1e9f;
            s[nt][3] = ((mk1 >> (c + 1)) & 1) ? s[nt][3] * scale : -1e9f;
            mx0 = fmaxf(mx0, fmaxf(s[nt][0], s[nt][1]));
            mx1 = fmaxf(mx1, fmaxf(s[nt][2], s[nt][3]));
        }
        mx0 = fmaxf(mx0, __shfl_xor_sync(0xffffffffu, mx0, 1));
        mx0 = fmaxf(mx0, __shfl_xor_sync(0xffffffffu, mx0, 2));
        mx1 = fmaxf(mx1, __shfl_xor_sync(0xffffffffu, mx1, 1));
        mx1 = fmaxf(mx1, __shfl_xor_sync(0xffffffffu, mx1, 2));

        float mn0 = fmaxf(m0, mx0), mn1 = fmaxf(m1, mx1);
        float corr0 = __expf(m0 - mn0), corr1 = __expf(m1 - mn1);
        float sum0 = 0.f, sum1 = 0.f;
#pragma unroll
        for (int nt = 0; nt < 8; nt++) {
            s[nt][0] = __expf(s[nt][0] - mn0);
            s[nt][1] = __expf(s[nt][1] - mn0);
            s[nt][2] = __expf(s[nt][2] - mn1);
            s[nt][3] = __expf(s[nt][3] - mn1);
            sum0 += s[nt][0] + s[nt][1];
            sum1 += s[nt][2] + s[nt][3];
        }
        sum0 += __shfl_xor_sync(0xffffffffu, sum0, 1);
        sum0 += __shfl_xor_sync(0xffffffffu, sum0, 2);
        sum1 += __shfl_xor_sync(0xffffffffu, sum1, 1);
        sum1 += __shfl_xor_sync(0xffffffffu, sum1, 2);
        l0 = l0 * corr0 + sum0;
        l1 = l1 * corr1 + sum1;
        m0 = mn0; m1 = mn1;

        // ---- O = O*corr + P @ K (P fragments from s registers) ----
#pragma unroll
        for (int nt = 0; nt < 8; nt++) {
            O[nt][0] *= corr0; O[nt][1] *= corr0;
            O[nt][2] *= corr1; O[nt][3] *= corr1;
        }
#pragma unroll
        for (int dt2 = 0; dt2 < 4; dt2++) {
            uint32_t af[4];
            af[0] = h2pack(s[2 * dt2][0],     s[2 * dt2][1]);
            af[1] = h2pack(s[2 * dt2][2],     s[2 * dt2][3]);
            af[2] = h2pack(s[2 * dt2 + 1][0], s[2 * dt2 + 1][1]);
            af[3] = h2pack(s[2 * dt2 + 1][2], s[2 * dt2 + 1][3]);
            const int krow = dt2 * 16 + krowl;
#pragma unroll
            for (int ntp = 0; ntp < 4; ntp++) {
                const int ncol = ntp * 16 + kcoll;
                uint32_t b0, b1, b2, b3;
                uint32_t addr = ksb + krow * AKP + ncol * 2;
                LDMX4T(b0, b1, b2, b3, addr);
                uint32_t bA[2] = {b0, b1}, bB[2] = {b2, b3};
                mma_f16(O[ntp * 2],     af, bA, O[ntp * 2]);
                mma_f16(O[ntp * 2 + 1], af, bB, O[ntp * 2 + 1]);
            }
        }
        __syncthreads();
    }

    // epilogue
    float inv0 = 1.f / l0, inv1 = 1.f / l1;
    __half* c0 = C + ((size_t)b * S_LEN + r0) * DMODEL + h * DK;
    __half* c1 = C + ((size_t)b * S_LEN + r1) * DMODEL + h * DK;
#pragma unroll
    for (int nt = 0; nt < 8; nt++) {
        int d = nt * 8 + 2 * q;
        *(__half2*)(c0 + d) = __floats2half2_rn(O[nt][0] * inv0, O[nt][1] * inv0);
        *(__half2*)(c1 + d) = __floats2half2_rn(O[nt][2] * inv1, O[nt][3] * inv1);
    }
}

// =====================================================================
// Launch
// =====================================================================
extern "C" void kernel_launch(void* const* d_in, const int* in_sizes, int n_in,
                              void* d_out, int out_size)
{
    const float* value = (const float*)d_in[0];
    const float* key   = (const float*)d_in[1];
    const float* query = (const float*)d_in[2];
    const int*   mask  = (const int*)  d_in[3];
    const float* Wv = (const float*)d_in[4];
    const float* bv = (const float*)d_in[5];
    const float* Wk = (const float*)d_in[6];
    const float* bk = (const float*)d_in[7];
    const float* Wq = (const float*)d_in[8];
    const float* bq = (const float*)d_in[9];
    const float* Wo = (const float*)d_in[10];
    const float* bo = (const float*)d_in[11];
    float* out = (float*)d_out;

    __half *hq, *hk, *hv, *hwq, *hwk, *hwv, *hwo, *qp, *vp, *kp, *att;
    uint32_t* mb;
    cudaGetSymbolAddress((void**)&hq,  g_hq);
    cudaGetSymbolAddress((void**)&hk,  g_hk);
    cudaGetSymbolAddress((void**)&hv,  g_hv);
    cudaGetSymbolAddress((void**)&hwq, g_hwq);
    cudaGetSymbolAddress((void**)&hwk, g_hwk);
    cudaGetSymbolAddress((void**)&hwv, g_hwv);
    cudaGetSymbolAddress((void**)&hwo, g_hwo);
    cudaGetSymbolAddress((void**)&qp,  g_qp);
    cudaGetSymbolAddress((void**)&vp,  g_vp);
    cudaGetSymbolAddress((void**)&kp,  g_kp);
    cudaGetSymbolAddress((void**)&att, g_att);
    cudaGetSymbolAddress((void**)&mb,  g_mb);

    cudaFuncSetAttribute(proj_gemm_kernel, cudaFuncAttributeMaxDynamicSharedMemorySize,
                         GEMM_SMEM_BYTES);
    cudaFuncSetAttribute(out_gemm_kernel, cudaFuncAttributeMaxDynamicSharedMemorySize,
                         GEMM_SMEM_BYTES);
    cudaFuncSetAttribute(attn_kernel, cudaFuncAttributeMaxDynamicSharedMemorySize,
                         ATTN_SMEM_BYTES);

    cvt_kernel<<<dim3(2048, 7), 256>>>(query, value, key, Wq, Wv, Wk, Wo,
                                       hq, hv, hk, hwq, hwv, hwk, hwo);
    maskbits_kernel<<<MROWS / 8, 256>>>(mask, mb);

    proj_gemm_kernel<<<dim3(8, 32, 3), 256, GEMM_SMEM_BYTES>>>(
        hq, hv, hk, hwq, hwv, hwk, bq, bv, bk, qp, vp, kp);

    attn_kernel<<<dim3(S_LEN / 128, NHEADS, BATCH), 256, ATTN_SMEM_BYTES>>>(
        qp, vp, kp, mb, att);

    out_gemm_kernel<<<dim3(8, 32), 256, GEMM_SMEM_BYTES>>>(att, hwo, bo, out);
}